// round 12
// baseline (speedup 1.0000x reference)
#include <cuda_runtime.h>
#include <cuda_fp16.h>
#include <stdint.h>

#define N 4096
#define D 768
#define BM 128
#define BN 128
#define BKH 64            // halfs per pipeline stage
#define NSTG (D / BKH)    // 12
#define MARGIN 1.0f
#define SH 72             // halfs per smem row (144 B) - conflict-free pad
#define BUF_HALFS (128 * SH)            // 9216 halfs = 18432 B
#define SMEM_BYTES (4 * BUF_HALFS * 2)  // 73728

#define NTILE 32          // 4096/128
#define NUNITS (NTILE * (NTILE + 1) / 2)  // 528 triangle units
#define NCTA (NUNITS / 2)                 // 264 CTAs, 2 units each (one wave)

__device__ __align__(128) __half g_e[N * D];  // normalized fp16 embeddings
__device__ float g_pkey[N];  // min positive dot + 4 (inf if none)
__device__ float g_nkey[N];  // max negative dot + 4 (0 if none)
__device__ unsigned int g_done = 0;
__device__ unsigned int g_ready[NTILE];  // per-128-row-block normalize flags

// ---------------- PTX helpers ---------------------------------------------
__device__ __forceinline__ uint32_t smem_u32(const void* p) {
    uint32_t a;
    asm("{ .reg .u64 t; cvta.to.shared.u64 t, %1; cvt.u32.u64 %0, t; }"
        : "=r"(a) : "l"(p));
    return a;
}
#define CP_ASYNC16(dst, src) \
    asm volatile("cp.async.cg.shared.global [%0], [%1], 16;" \
                 :: "r"(dst), "l"(src) : "memory")
#define CP_COMMIT() asm volatile("cp.async.commit_group;" ::: "memory")
#define CP_WAIT(n)  asm volatile("cp.async.wait_group %0;" :: "n"(n) : "memory")

#define LDSM_X4(r0, r1, r2, r3, addr) \
    asm volatile("ldmatrix.sync.aligned.m8n8.x4.shared.b16 {%0,%1,%2,%3}, [%4];" \
                 : "=r"(r0), "=r"(r1), "=r"(r2), "=r"(r3) : "r"(addr))

__device__ __forceinline__ void mma_f16(float* d, const uint32_t* a,
                                        const uint32_t* b) {
    asm volatile(
        "mma.sync.aligned.m16n8k16.row.col.f32.f16.f16.f32 "
        "{%0,%1,%2,%3}, {%4,%5,%6,%7}, {%8,%9}, {%0,%1,%2,%3};"
        : "+f"(d[0]), "+f"(d[1]), "+f"(d[2]), "+f"(d[3])
        : "r"(a[0]), "r"(a[1]), "r"(a[2]), "r"(a[3]), "r"(b[0]), "r"(b[1]));
}

// ---------------------------------------------------------------------------
// Fused kernel, no global barrier. CTAs 0..31 each normalize one 128-row
// block and raise a ready flag; every CTA spin-waits only on the blocks its
// two triangle tiles need. Mainloop/epilogue identical to the best (R8)
// version: two 128x128 Gram tiles per CTA, fp16 m16n8k16 MMA, double-
// buffered cp.async; batch-hard mining in dot domain; last CTA finalizes.
__global__ void __launch_bounds__(256, 2)
mine_mma(const float* __restrict__ emb, const long long* __restrict__ labels,
         float* __restrict__ out) {
    extern __shared__ __half smem[];
    const uint32_t sb = smem_u32(smem);
    __shared__ int s_lr[128], s_lc[128];
    __shared__ int s_last;

    const int tid = threadIdx.x;
    const int lane = tid & 31;
    const int warp = tid >> 5;
    const int wy = warp >> 2;   // 0..1
    const int wx = warp & 3;    // 0..3
    const int g = lane >> 2;    // 0..7
    const int t = lane & 3;     // 0..3

    // ---- triangle mapping for this CTA's two units (computed up front) ----
    int I0, J0, I1, J1;
    {
        int u = blockIdx.x * 2;
        int I = 0;
        while (u >= NTILE - I) { u -= NTILE - I; I++; }
        I0 = I; J0 = I + u;
        u++;
        if (u >= NTILE - I) { u -= NTILE - I; I++; }
        I1 = I; J1 = I + u;
    }

    // ---- phase 0: CTAs 0..31 normalize one 128-row block ------------------
    if (blockIdx.x < NTILE) {
        const int base = blockIdx.x * 128;
#pragma unroll
        for (int r16 = 0; r16 < 16; r16++) {
            const int row = base + warp * 16 + r16;
            if (lane == 0) {
                g_pkey[row] = __int_as_float(0x7f800000);
                g_nkey[row] = 0.0f;
            }
            const float4* src = (const float4*)(emb + (size_t)row * D);
            float4 v[6];
            float s = 0.0f;
#pragma unroll
            for (int i = 0; i < 6; i++) {
                v[i] = src[lane + i * 32];
                s += v[i].x * v[i].x + v[i].y * v[i].y + v[i].z * v[i].z +
                     v[i].w * v[i].w;
            }
#pragma unroll
            for (int o = 16; o > 0; o >>= 1)
                s += __shfl_xor_sync(0xffffffffu, s, o);
            float inv = 1.0f / fmaxf(sqrtf(s), 1e-12f);
            uint2* dst = (uint2*)(g_e + (size_t)row * D);
#pragma unroll
            for (int i = 0; i < 6; i++) {
                __half2 h01 = __floats2half2_rn(v[i].x * inv, v[i].y * inv);
                __half2 h23 = __floats2half2_rn(v[i].z * inv, v[i].w * inv);
                uint2 u2;
                u2.x = *reinterpret_cast<uint32_t*>(&h01);
                u2.y = *reinterpret_cast<uint32_t*>(&h23);
                dst[lane + i * 32] = u2;
            }
        }
        __threadfence();
        __syncthreads();
        if (tid == 0) atomicExch(&g_ready[blockIdx.x], 1u);
    }

    // ---- wait for the row blocks this CTA consumes -------------------------
    if (tid == 0) {
        while (!*(volatile unsigned int*)&g_ready[I0]) __nanosleep(32);
        while (!*(volatile unsigned int*)&g_ready[J0]) __nanosleep(32);
        while (!*(volatile unsigned int*)&g_ready[I1]) __nanosleep(32);
        while (!*(volatile unsigned int*)&g_ready[J1]) __nanosleep(32);
    }
    __syncthreads();
    __threadfence();

    // per-lane LDSM base offsets (half units within a buffer)
    const int aRowOff = (wy * 64 + (lane & 15)) * SH + (lane >> 4) * 8;
    const int bRowOff = (wx * 32 + (lane >> 4) * 8 + (lane & 7)) * SH +
                        ((lane >> 3) & 1) * 8;

    for (int unit_i = 0; unit_i < 2; unit_i++) {
        const int rowBase = (unit_i ? I1 : I0) * BM;
        const int colBase = (unit_i ? J1 : J0) * BN;

        __syncthreads();  // previous unit done with smem (labels + buffers)
        if (tid < 128) s_lr[tid] = (int)labels[rowBase + tid];
        else s_lc[tid - 128] = (int)labels[colBase + tid - 128];

        float acc[4][4][4];
#pragma unroll
        for (int mt = 0; mt < 4; mt++)
#pragma unroll
            for (int nt = 0; nt < 4; nt++)
#pragma unroll
                for (int q = 0; q < 4; q++) acc[mt][nt][q] = 0.0f;

        // ---- prefetch stage 0 ----
        {
            const __half* srcA = g_e + (size_t)rowBase * D;
            const __half* srcB = g_e + (size_t)colBase * D;
#pragma unroll
            for (int i = 0; i < 4; i++) {
                int idx = tid + i * 256;
                int row = idx >> 3, q = idx & 7;
                CP_ASYNC16(sb + row * 144 + q * 16,
                           srcA + (size_t)row * D + q * 8);
                CP_ASYNC16(sb + 2 * BUF_HALFS * 2 + row * 144 + q * 16,
                           srcB + (size_t)row * D + q * 8);
            }
            CP_COMMIT();
        }

        for (int st = 0; st < NSTG; st++) {
            const int cur = st & 1;
            if (st + 1 < NSTG) {
                const int nxt = (st + 1) & 1;
                const int k0 = (st + 1) * BKH;
                const __half* srcA = g_e + (size_t)rowBase * D + k0;
                const __half* srcB = g_e + (size_t)colBase * D + k0;
#pragma unroll
                for (int i = 0; i < 4; i++) {
                    int idx = tid + i * 256;
                    int row = idx >> 3, q = idx & 7;
                    CP_ASYNC16(sb + nxt * BUF_HALFS * 2 + row * 144 + q * 16,
                               srcA + (size_t)row * D + q * 8);
                    CP_ASYNC16(
                        sb + (2 + nxt) * BUF_HALFS * 2 + row * 144 + q * 16,
                        srcB + (size_t)row * D + q * 8);
                }
                CP_COMMIT();
                CP_WAIT(1);
            } else {
                CP_WAIT(0);
            }
            __syncthreads();

            const uint32_t baseA = sb + cur * BUF_HALFS * 2;
            const uint32_t baseB = sb + (2 + cur) * BUF_HALFS * 2;
#pragma unroll
            for (int ks = 0; ks < 4; ks++) {
                uint32_t a[4][4], b[4][2];
#pragma unroll
                for (int mt = 0; mt < 4; mt++)
                    LDSM_X4(a[mt][0], a[mt][1], a[mt][2], a[mt][3],
                            baseA + (aRowOff + mt * 16 * SH + ks * 16) * 2);
#pragma unroll
                for (int p = 0; p < 2; p++)
                    LDSM_X4(b[2 * p][0], b[2 * p][1], b[2 * p + 1][0],
                            b[2 * p + 1][1],
                            baseB + (bRowOff + p * 16 * SH + ks * 16) * 2);
#pragma unroll
                for (int mt = 0; mt < 4; mt++)
#pragma unroll
                    for (int nt = 0; nt < 4; nt++)
                        mma_f16(acc[mt][nt], a[mt], b[nt]);
            }
            __syncthreads();
        }

        // ---- mining: rows and cols are both anchors ----------------------
        const float INF = __int_as_float(0x7f800000);
        float rp[4][2], rn[4][2];
        float cpm[4][2], cnm[4][2];
#pragma unroll
        for (int i = 0; i < 4; i++)
#pragma unroll
            for (int h = 0; h < 2; h++) {
                rp[i][h] = INF; rn[i][h] = -INF;
                cpm[i][h] = INF; cnm[i][h] = -INF;
            }

#pragma unroll
        for (int nt = 0; nt < 4; nt++) {
            const int c0 = colBase + wx * 32 + nt * 8 + 2 * t;
            const int lc0 = s_lc[wx * 32 + nt * 8 + 2 * t];
            const int lc1 = s_lc[wx * 32 + nt * 8 + 2 * t + 1];
#pragma unroll
            for (int mt = 0; mt < 4; mt++) {
                const int r0 = rowBase + wy * 64 + mt * 16 + g;
                const int r1 = r0 + 8;
                const int lr0 = s_lr[wy * 64 + mt * 16 + g];
                const int lr1 = s_lr[wy * 64 + mt * 16 + g + 8];
                const float d0 = acc[mt][nt][0], d1 = acc[mt][nt][1];
                const float d2 = acc[mt][nt][2], d3 = acc[mt][nt][3];
                if (lr0 == lc0) {
                    if (r0 != c0) { rp[mt][0] = fminf(rp[mt][0], d0);
                                    cpm[nt][0] = fminf(cpm[nt][0], d0); }
                } else { rn[mt][0] = fmaxf(rn[mt][0], d0);
                         cnm[nt][0] = fmaxf(cnm[nt][0], d0); }
                if (lr0 == lc1) {
                    if (r0 != c0 + 1) { rp[mt][0] = fminf(rp[mt][0], d1);
                                        cpm[nt][1] = fminf(cpm[nt][1], d1); }
                } else { rn[mt][0] = fmaxf(rn[mt][0], d1);
                         cnm[nt][1] = fmaxf(cnm[nt][1], d1); }
                if (lr1 == lc0) {
                    if (r1 != c0) { rp[mt][1] = fminf(rp[mt][1], d2);
                                    cpm[nt][0] = fminf(cpm[nt][0], d2); }
                } else { rn[mt][1] = fmaxf(rn[mt][1], d2);
                         cnm[nt][0] = fmaxf(cnm[nt][0], d2); }
                if (lr1 == lc1) {
                    if (r1 != c0 + 1) { rp[mt][1] = fminf(rp[mt][1], d3);
                                        cpm[nt][1] = fminf(cpm[nt][1], d3); }
                } else { rn[mt][1] = fmaxf(rn[mt][1], d3);
                         cnm[nt][1] = fmaxf(cnm[nt][1], d3); }
            }
        }

        // row-anchor reduce across t lanes
#pragma unroll
        for (int mt = 0; mt < 4; mt++)
#pragma unroll
            for (int h = 0; h < 2; h++) {
                float p = rp[mt][h], n = rn[mt][h];
                p = fminf(p, __shfl_xor_sync(0xffffffffu, p, 1));
                p = fminf(p, __shfl_xor_sync(0xffffffffu, p, 2));
                n = fmaxf(n, __shfl_xor_sync(0xffffffffu, n, 1));
                n = fmaxf(n, __shfl_xor_sync(0xffffffffu, n, 2));
                if (t == 0) {
                    int r = rowBase + wy * 64 + mt * 16 + g + h * 8;
                    if (p < 1e30f)
                        atomicMin(reinterpret_cast<int*>(&g_pkey[r]),
                                  __float_as_int(p + 4.0f));
                    if (n > -1e30f)
                        atomicMax(reinterpret_cast<int*>(&g_nkey[r]),
                                  __float_as_int(n + 4.0f));
                }
            }

        // col-anchor reduce across g lanes
#pragma unroll
        for (int nt = 0; nt < 4; nt++)
#pragma unroll
            for (int h = 0; h < 2; h++) {
                float p = cpm[nt][h], n = cnm[nt][h];
                p = fminf(p, __shfl_xor_sync(0xffffffffu, p, 4));
                p = fminf(p, __shfl_xor_sync(0xffffffffu, p, 8));
                p = fminf(p, __shfl_xor_sync(0xffffffffu, p, 16));
                n = fmaxf(n, __shfl_xor_sync(0xffffffffu, n, 4));
                n = fmaxf(n, __shfl_xor_sync(0xffffffffu, n, 8));
                n = fmaxf(n, __shfl_xor_sync(0xffffffffu, n, 16));
                if (g == 0) {
                    int c = colBase + wx * 32 + nt * 8 + 2 * t + h;
                    if (p < 1e30f)
                        atomicMin(reinterpret_cast<int*>(&g_pkey[c]),
                                  __float_as_int(p + 4.0f));
                    if (n > -1e30f)
                        atomicMax(reinterpret_cast<int*>(&g_nkey[c]),
                                  __float_as_int(n + 4.0f));
                }
            }
    }

    // ---- last CTA computes the final loss ---------------------------------
    __threadfence();
    __syncthreads();
    if (tid == 0) {
        unsigned int v = atomicAdd(&g_done, 1u);
        s_last = (v == NCTA - 1);
    }
    __syncthreads();
    if (!s_last) return;
    __threadfence();

    float sum = 0.0f, cnt = 0.0f;
    for (int i = tid; i < N; i += 256) {
        float pk = g_pkey[i];
        float nk = g_nkey[i];
        if (pk < 1e30f) {
            cnt += 1.0f;
            float dap = sqrtf(fmaxf(2.0f - 2.0f * (pk - 4.0f), 0.0f) + 1e-12f);
            float dan = (nk > 0.0f)
                ? sqrtf(fmaxf(2.0f - 2.0f * (nk - 4.0f), 0.0f) + 1e-12f)
                : 1e30f;
            sum += fmaxf(dap - dan + MARGIN, 0.0f);
        }
    }
#pragma unroll
    for (int o = 16; o > 0; o >>= 1) {
        sum += __shfl_xor_sync(0xffffffffu, sum, o);
        cnt += __shfl_xor_sync(0xffffffffu, cnt, o);
    }
    __shared__ float rs[8], rc[8];
    if ((tid & 31) == 0) { rs[tid >> 5] = sum; rc[tid >> 5] = cnt; }
    __syncthreads();
    if (tid < NTILE) g_ready[tid] = 0;  // reset flags for next graph replay
    if (tid == 0) {
        float S = 0.0f, C = 0.0f;
#pragma unroll
        for (int w = 0; w < 8; w++) { S += rs[w]; C += rc[w]; }
        out[0] = S / fmaxf(C, 1.0f);
        g_done = 0;  // reset for next graph replay
    }
}

// ---------------------------------------------------------------------------
extern "C" void kernel_launch(void* const* d_in, const int* in_sizes, int n_in,
                              void* d_out, int out_size) {
    const float* emb = (const float*)d_in[0];
    const long long* labels = (const long long*)d_in[1];
    float* out = (float*)d_out;

    static int configured = 0;
    if (!configured) {
        cudaFuncSetAttribute(mine_mma, cudaFuncAttributeMaxDynamicSharedMemorySize,
                             SMEM_BYTES);
        configured = 1;
    }

    mine_mma<<<NCTA, 256, SMEM_BYTES>>>(emb, labels, out);
}

// round 13
// speedup vs baseline: 1.0847x; 1.0847x over previous
#include <cuda_runtime.h>
#include <cuda_fp16.h>
#include <stdint.h>

#define N 4096
#define D 768
#define BM 128
#define BN 128
#define BKH 64            // halfs per pipeline stage
#define NSTG (D / BKH)    // 12
#define MARGIN 1.0f
#define SH 72             // halfs per smem row (144 B) - conflict-free pad
#define BUF_HALFS (128 * SH)            // 9216 halfs = 18432 B
#define SMEM_BYTES (4 * BUF_HALFS * 2)  // 73728

#define NTILE 32          // 4096/128
#define NUNITS (NTILE * (NTILE + 1) / 2)  // 528 triangle units
#define NCTA (NUNITS / 2)                 // 264 CTAs, 2 units each (one wave)

__device__ __align__(128) __half g_e[N * D];  // normalized fp16 embeddings
__device__ float g_pkey[N];  // min positive dot + 4 (inf if none)
__device__ float g_nkey[N];  // max negative dot + 4 (0 if none)
__device__ unsigned int g_done = 0;

// ---------------- PTX helpers ---------------------------------------------
__device__ __forceinline__ uint32_t smem_u32(const void* p) {
    uint32_t a;
    asm("{ .reg .u64 t; cvta.to.shared.u64 t, %1; cvt.u32.u64 %0, t; }"
        : "=r"(a) : "l"(p));
    return a;
}
#define CP_ASYNC16(dst, src) \
    asm volatile("cp.async.cg.shared.global [%0], [%1], 16;" \
                 :: "r"(dst), "l"(src) : "memory")
#define CP_COMMIT() asm volatile("cp.async.commit_group;" ::: "memory")
#define CP_WAIT(n)  asm volatile("cp.async.wait_group %0;" :: "n"(n) : "memory")

#define LDSM_X4(r0, r1, r2, r3, addr) \
    asm volatile("ldmatrix.sync.aligned.m8n8.x4.shared.b16 {%0,%1,%2,%3}, [%4];" \
                 : "=r"(r0), "=r"(r1), "=r"(r2), "=r"(r3) : "r"(addr))

__device__ __forceinline__ void mma_f16(float* d, const uint32_t* a,
                                        const uint32_t* b) {
    asm volatile(
        "mma.sync.aligned.m16n8k16.row.col.f32.f16.f16.f32 "
        "{%0,%1,%2,%3}, {%4,%5,%6,%7}, {%8,%9}, {%0,%1,%2,%3};"
        : "+f"(d[0]), "+f"(d[1]), "+f"(d[2]), "+f"(d[3])
        : "r"(a[0]), "r"(a[1]), "r"(a[2]), "r"(a[3]), "r"(b[0]), "r"(b[1]));
}

// ---------------------------------------------------------------------------
// Warp-per-row normalize + fp16 convert; inits per-row mining keys.
__global__ void normalize_kernel(const float* __restrict__ emb) {
    const int warp = threadIdx.x >> 5;
    const int lane = threadIdx.x & 31;
    const int row = blockIdx.x * 8 + warp;
    if (lane == 0) {
        g_pkey[row] = __int_as_float(0x7f800000);  // +inf
        g_nkey[row] = 0.0f;                        // sentinel
    }
    const float4* src = (const float4*)(emb + (size_t)row * D);
    float4 v[6];
    float s = 0.0f;
#pragma unroll
    for (int i = 0; i < 6; i++) {
        v[i] = src[lane + i * 32];
        s += v[i].x * v[i].x + v[i].y * v[i].y + v[i].z * v[i].z +
             v[i].w * v[i].w;
    }
#pragma unroll
    for (int o = 16; o > 0; o >>= 1) s += __shfl_xor_sync(0xffffffffu, s, o);
    float inv = 1.0f / fmaxf(sqrtf(s), 1e-12f);
    uint2* dst = (uint2*)(g_e + (size_t)row * D);
#pragma unroll
    for (int i = 0; i < 6; i++) {
        __half2 h01 = __floats2half2_rn(v[i].x * inv, v[i].y * inv);
        __half2 h23 = __floats2half2_rn(v[i].z * inv, v[i].w * inv);
        uint2 u;
        u.x = *reinterpret_cast<uint32_t*>(&h01);
        u.y = *reinterpret_cast<uint32_t*>(&h23);
        dst[lane + i * 32] = u;
    }
}

// ---------------------------------------------------------------------------
// Issue one stage of cp.async loads (A and B tiles) into ring slot `slot`.
__device__ __forceinline__ void issue_stage(uint32_t sb, int slot, int rowBase,
                                            int colBase, int k0, int tid) {
    const __half* srcA = g_e + (size_t)rowBase * D + k0;
    const __half* srcB = g_e + (size_t)colBase * D + k0;
#pragma unroll
    for (int i = 0; i < 4; i++) {
        int idx = tid + i * 256;
        int row = idx >> 3, q = idx & 7;
        CP_ASYNC16(sb + slot * BUF_HALFS * 2 + row * 144 + q * 16,
                   srcA + (size_t)row * D + q * 8);
        CP_ASYNC16(sb + (2 + slot) * BUF_HALFS * 2 + row * 144 + q * 16,
                   srcB + (size_t)row * D + q * 8);
    }
}

// ---------------------------------------------------------------------------
// Two upper-triangle 128x128 Gram tiles per CTA (single wave). fp16
// m16n8k16 MMA via ldmatrix, double-buffered cp.async pipeline (R8
// structure). Unit 1's stage-0 prefetch is issued during unit 0's last
// stage so it overlaps the mining epilogue. Batch-hard mining in dot
// domain; last CTA computes the final scalar loss.
__global__ void __launch_bounds__(256, 2)
mine_mma(const long long* __restrict__ labels, float* __restrict__ out) {
    extern __shared__ __half smem[];
    const uint32_t sb = smem_u32(smem);
    __shared__ int s_lr[128], s_lc[128];
    __shared__ int s_last;

    const int tid = threadIdx.x;
    const int lane = tid & 31;
    const int warp = tid >> 5;
    const int wy = warp >> 2;   // 0..1
    const int wx = warp & 3;    // 0..3
    const int g = lane >> 2;    // 0..7
    const int t = lane & 3;     // 0..3

    // triangle mapping for both units, computed up front
    int I0, J0, I1, J1;
    {
        int u = blockIdx.x * 2;
        int I = 0;
        while (u >= NTILE - I) { u -= NTILE - I; I++; }
        I0 = I; J0 = I + u;
        u++;
        if (u >= NTILE - I) { u -= NTILE - I; I++; }
        I1 = I; J1 = I + u;
    }

    // per-lane LDSM base offsets (half units within a buffer)
    const int aRowOff = (wy * 64 + (lane & 15)) * SH + (lane >> 4) * 8;
    const int bRowOff = (wx * 32 + (lane >> 4) * 8 + (lane & 7)) * SH +
                        ((lane >> 3) & 1) * 8;

    // prefetch unit 0 stage 0
    issue_stage(sb, 0, I0 * BM, J0 * BN, 0, tid);
    CP_COMMIT();

    for (int unit_i = 0; unit_i < 2; unit_i++) {
        const int rowBase = (unit_i ? I1 : I0) * BM;
        const int colBase = (unit_i ? J1 : J0) * BN;

        __syncthreads();  // previous unit done with smem (labels)
        if (tid < 128) s_lr[tid] = (int)labels[rowBase + tid];
        else s_lc[tid - 128] = (int)labels[colBase + tid - 128];

        float acc[4][4][4];
#pragma unroll
        for (int mt = 0; mt < 4; mt++)
#pragma unroll
            for (int nt = 0; nt < 4; nt++)
#pragma unroll
                for (int q = 0; q < 4; q++) acc[mt][nt][q] = 0.0f;

        for (int st = 0; st < NSTG; st++) {
            const int cur = st & 1;
            if (st + 1 < NSTG) {
                issue_stage(sb, st & 1 ? 0 : 1, rowBase, colBase,
                            (st + 1) * BKH, tid);
                CP_COMMIT();
                CP_WAIT(1);
            } else if (unit_i == 0) {
                // overlap: issue unit 1's stage 0 into slot 0 (free since
                // stage NSTG-2's compute finished at the last barrier)
                issue_stage(sb, 0, I1 * BM, J1 * BN, 0, tid);
                CP_COMMIT();
                CP_WAIT(1);  // one newer group pending -> stage NSTG-1 ready
            } else {
                CP_WAIT(0);
            }
            __syncthreads();

            const uint32_t baseA = sb + cur * BUF_HALFS * 2;
            const uint32_t baseB = sb + (2 + cur) * BUF_HALFS * 2;
#pragma unroll
            for (int ks = 0; ks < 4; ks++) {
                uint32_t a[4][4], b[4][2];
#pragma unroll
                for (int mt = 0; mt < 4; mt++)
                    LDSM_X4(a[mt][0], a[mt][1], a[mt][2], a[mt][3],
                            baseA + (aRowOff + mt * 16 * SH + ks * 16) * 2);
#pragma unroll
                for (int p = 0; p < 2; p++)
                    LDSM_X4(b[2 * p][0], b[2 * p][1], b[2 * p + 1][0],
                            b[2 * p + 1][1],
                            baseB + (bRowOff + p * 16 * SH + ks * 16) * 2);
#pragma unroll
                for (int mt = 0; mt < 4; mt++)
#pragma unroll
                    for (int nt = 0; nt < 4; nt++)
                        mma_f16(acc[mt][nt], a[mt], b[nt]);
            }
            __syncthreads();
        }

        // ---- mining: rows and cols are both anchors ----------------------
        const float INF = __int_as_float(0x7f800000);
        float rp[4][2], rn[4][2];
        float cpm[4][2], cnm[4][2];
#pragma unroll
        for (int i = 0; i < 4; i++)
#pragma unroll
            for (int h = 0; h < 2; h++) {
                rp[i][h] = INF; rn[i][h] = -INF;
                cpm[i][h] = INF; cnm[i][h] = -INF;
            }

#pragma unroll
        for (int nt = 0; nt < 4; nt++) {
            const int c0 = colBase + wx * 32 + nt * 8 + 2 * t;
            const int lc0 = s_lc[wx * 32 + nt * 8 + 2 * t];
            const int lc1 = s_lc[wx * 32 + nt * 8 + 2 * t + 1];
#pragma unroll
            for (int mt = 0; mt < 4; mt++) {
                const int r0 = rowBase + wy * 64 + mt * 16 + g;
                const int r1 = r0 + 8;
                const int lr0 = s_lr[wy * 64 + mt * 16 + g];
                const int lr1 = s_lr[wy * 64 + mt * 16 + g + 8];
                const float d0 = acc[mt][nt][0], d1 = acc[mt][nt][1];
                const float d2 = acc[mt][nt][2], d3 = acc[mt][nt][3];
                if (lr0 == lc0) {
                    if (r0 != c0) { rp[mt][0] = fminf(rp[mt][0], d0);
                                    cpm[nt][0] = fminf(cpm[nt][0], d0); }
                } else { rn[mt][0] = fmaxf(rn[mt][0], d0);
                         cnm[nt][0] = fmaxf(cnm[nt][0], d0); }
                if (lr0 == lc1) {
                    if (r0 != c0 + 1) { rp[mt][0] = fminf(rp[mt][0], d1);
                                        cpm[nt][1] = fminf(cpm[nt][1], d1); }
                } else { rn[mt][0] = fmaxf(rn[mt][0], d1);
                         cnm[nt][1] = fmaxf(cnm[nt][1], d1); }
                if (lr1 == lc0) {
                    if (r1 != c0) { rp[mt][1] = fminf(rp[mt][1], d2);
                                    cpm[nt][0] = fminf(cpm[nt][0], d2); }
                } else { rn[mt][1] = fmaxf(rn[mt][1], d2);
                         cnm[nt][0] = fmaxf(cnm[nt][0], d2); }
                if (lr1 == lc1) {
                    if (r1 != c0 + 1) { rp[mt][1] = fminf(rp[mt][1], d3);
                                        cpm[nt][1] = fminf(cpm[nt][1], d3); }
                } else { rn[mt][1] = fmaxf(rn[mt][1], d3);
                         cnm[nt][1] = fmaxf(cnm[nt][1], d3); }
            }
        }

        // row-anchor reduce across t lanes
#pragma unroll
        for (int mt = 0; mt < 4; mt++)
#pragma unroll
            for (int h = 0; h < 2; h++) {
                float p = rp[mt][h], n = rn[mt][h];
                p = fminf(p, __shfl_xor_sync(0xffffffffu, p, 1));
                p = fminf(p, __shfl_xor_sync(0xffffffffu, p, 2));
                n = fmaxf(n, __shfl_xor_sync(0xffffffffu, n, 1));
                n = fmaxf(n, __shfl_xor_sync(0xffffffffu, n, 2));
                if (t == 0) {
                    int r = rowBase + wy * 64 + mt * 16 + g + h * 8;
                    if (p < 1e30f)
                        atomicMin(reinterpret_cast<int*>(&g_pkey[r]),
                                  __float_as_int(p + 4.0f));
                    if (n > -1e30f)
                        atomicMax(reinterpret_cast<int*>(&g_nkey[r]),
                                  __float_as_int(n + 4.0f));
                }
            }

        // col-anchor reduce across g lanes
#pragma unroll
        for (int nt = 0; nt < 4; nt++)
#pragma unroll
            for (int h = 0; h < 2; h++) {
                float p = cpm[nt][h], n = cnm[nt][h];
                p = fminf(p, __shfl_xor_sync(0xffffffffu, p, 4));
                p = fminf(p, __shfl_xor_sync(0xffffffffu, p, 8));
                p = fminf(p, __shfl_xor_sync(0xffffffffu, p, 16));
                n = fmaxf(n, __shfl_xor_sync(0xffffffffu, n, 4));
                n = fmaxf(n, __shfl_xor_sync(0xffffffffu, n, 8));
                n = fmaxf(n, __shfl_xor_sync(0xffffffffu, n, 16));
                if (g == 0) {
                    int c = colBase + wx * 32 + nt * 8 + 2 * t + h;
                    if (p < 1e30f)
                        atomicMin(reinterpret_cast<int*>(&g_pkey[c]),
                                  __float_as_int(p + 4.0f));
                    if (n > -1e30f)
                        atomicMax(reinterpret_cast<int*>(&g_nkey[c]),
                                  __float_as_int(n + 4.0f));
                }
            }
    }

    // ---- last CTA computes the final loss ---------------------------------
    __threadfence();
    __syncthreads();
    if (tid == 0) {
        unsigned int v = atomicAdd(&g_done, 1u);
        s_last = (v == NCTA - 1);
    }
    __syncthreads();
    if (!s_last) return;
    __threadfence();

    float sum = 0.0f, cnt = 0.0f;
    for (int i = tid; i < N; i += 256) {
        float pk = g_pkey[i];
        float nk = g_nkey[i];
        if (pk < 1e30f) {
            cnt += 1.0f;
            float dap = sqrtf(fmaxf(2.0f - 2.0f * (pk - 4.0f), 0.0f) + 1e-12f);
            float dan = (nk > 0.0f)
                ? sqrtf(fmaxf(2.0f - 2.0f * (nk - 4.0f), 0.0f) + 1e-12f)
                : 1e30f;
            sum += fmaxf(dap - dan + MARGIN, 0.0f);
        }
    }
#pragma unroll
    for (int o = 16; o > 0; o >>= 1) {
        sum += __shfl_xor_sync(0xffffffffu, sum, o);
        cnt += __shfl_xor_sync(0xffffffffu, cnt, o);
    }
    __shared__ float rs[8], rc[8];
    if ((tid & 31) == 0) { rs[tid >> 5] = sum; rc[tid >> 5] = cnt; }
    __syncthreads();
    if (tid == 0) {
        float S = 0.0f, C = 0.0f;
#pragma unroll
        for (int w = 0; w < 8; w++) { S += rs[w]; C += rc[w]; }
        out[0] = S / fmaxf(C, 1.0f);
        g_done = 0;  // reset for next graph replay
    }
}

// ---------------------------------------------------------------------------
extern "C" void kernel_launch(void* const* d_in, const int* in_sizes, int n_in,
                              void* d_out, int out_size) {
    const float* emb = (const float*)d_in[0];
    const long long* labels = (const long long*)d_in[1];
    float* out = (float*)d_out;

    static int configured = 0;
    if (!configured) {
        cudaFuncSetAttribute(mine_mma, cudaFuncAttributeMaxDynamicSharedMemorySize,
                             SMEM_BYTES);
        configured = 1;
    }

    normalize_kernel<<<N / 8, 256>>>(emb);
    mine_mma<<<NCTA, 256, SMEM_BYTES>>>(labels, out);
}

// round 14
// speedup vs baseline: 1.0868x; 1.0019x over previous
#include <cuda_runtime.h>
#include <cuda_fp16.h>
#include <stdint.h>

#define N 4096
#define D 768
#define BM 128
#define BN 128
#define BKH 64            // halfs per pipeline stage
#define NSTG (D / BKH)    // 12
#define MARGIN 1.0f
#define SH 72             // halfs per smem row (144 B) - conflict-free pad
#define BUF_HALFS (128 * SH)            // 9216 halfs = 18432 B
#define SMEM_BYTES (4 * BUF_HALFS * 2)  // 73728

#define NTILE 32          // 4096/128
#define NUNITS (NTILE * (NTILE + 1) / 2)  // 528 triangle units
#define NCTA (NUNITS / 2)                 // 264 CTAs, 2 units each (one wave)

__device__ __align__(128) __half g_e[N * D];  // normalized fp16 embeddings
__device__ float g_pkey[N];  // min positive dot + 4 (inf if none)
__device__ float g_nkey[N];  // max negative dot + 4 (0 if none)
__device__ unsigned int g_done = 0;

// ---------------- PTX helpers ---------------------------------------------
__device__ __forceinline__ uint32_t smem_u32(const void* p) {
    uint32_t a;
    asm("{ .reg .u64 t; cvta.to.shared.u64 t, %1; cvt.u32.u64 %0, t; }"
        : "=r"(a) : "l"(p));
    return a;
}
#define CP_ASYNC16(dst, src) \
    asm volatile("cp.async.cg.shared.global [%0], [%1], 16;" \
                 :: "r"(dst), "l"(src) : "memory")
#define CP_COMMIT() asm volatile("cp.async.commit_group;" ::: "memory")
#define CP_WAIT(n)  asm volatile("cp.async.wait_group %0;" :: "n"(n) : "memory")

#define LDSM_X4(r0, r1, r2, r3, addr) \
    asm volatile("ldmatrix.sync.aligned.m8n8.x4.shared.b16 {%0,%1,%2,%3}, [%4];" \
                 : "=r"(r0), "=r"(r1), "=r"(r2), "=r"(r3) : "r"(addr))

__device__ __forceinline__ void mma_f16(float* d, const uint32_t* a,
                                        const uint32_t* b) {
    asm volatile(
        "mma.sync.aligned.m16n8k16.row.col.f32.f16.f16.f32 "
        "{%0,%1,%2,%3}, {%4,%5,%6,%7}, {%8,%9}, {%0,%1,%2,%3};"
        : "+f"(d[0]), "+f"(d[1]), "+f"(d[2]), "+f"(d[3])
        : "r"(a[0]), "r"(a[1]), "r"(a[2]), "r"(a[3]), "r"(b[0]), "r"(b[1]));
}

// ---------------------------------------------------------------------------
// Warp-per-row normalize + fp16 convert; inits per-row mining keys.
__global__ void normalize_kernel(const float* __restrict__ emb) {
    const int warp = threadIdx.x >> 5;
    const int lane = threadIdx.x & 31;
    const int row = blockIdx.x * 8 + warp;
    if (lane == 0) {
        g_pkey[row] = __int_as_float(0x7f800000);  // +inf
        g_nkey[row] = 0.0f;                        // sentinel
    }
    const float4* src = (const float4*)(emb + (size_t)row * D);
    float4 v[6];
    float s = 0.0f;
#pragma unroll
    for (int i = 0; i < 6; i++) {
        v[i] = src[lane + i * 32];
        s += v[i].x * v[i].x + v[i].y * v[i].y + v[i].z * v[i].z +
             v[i].w * v[i].w;
    }
#pragma unroll
    for (int o = 16; o > 0; o >>= 1) s += __shfl_xor_sync(0xffffffffu, s, o);
    float inv = 1.0f / fmaxf(sqrtf(s), 1e-12f);
    uint2* dst = (uint2*)(g_e + (size_t)row * D);
#pragma unroll
    for (int i = 0; i < 6; i++) {
        __half2 h01 = __floats2half2_rn(v[i].x * inv, v[i].y * inv);
        __half2 h23 = __floats2half2_rn(v[i].z * inv, v[i].w * inv);
        uint2 u;
        u.x = *reinterpret_cast<uint32_t*>(&h01);
        u.y = *reinterpret_cast<uint32_t*>(&h23);
        dst[lane + i * 32] = u;
    }
}

// ---------------------------------------------------------------------------
// Two upper-triangle 128x128 Gram tiles per CTA (single wave). fp16
// m16n8k16 MMA via ldmatrix, double-buffered cp.async pipeline (R8
// structure). Diagonal tiles (rowBase == colBase) skip the redundant B-side
// loads and alias the A buffer. Batch-hard mining in dot domain; last CTA
// computes the final scalar loss.
__global__ void __launch_bounds__(256, 2)
mine_mma(const long long* __restrict__ labels, float* __restrict__ out) {
    extern __shared__ __half smem[];
    const uint32_t sb = smem_u32(smem);
    __shared__ int s_lr[128], s_lc[128];
    __shared__ int s_last;

    const int tid = threadIdx.x;
    const int lane = tid & 31;
    const int warp = tid >> 5;
    const int wy = warp >> 2;   // 0..1
    const int wx = warp & 3;    // 0..3
    const int g = lane >> 2;    // 0..7
    const int t = lane & 3;     // 0..3

    // per-lane LDSM base offsets (half units within a buffer)
    const int aRowOff = (wy * 64 + (lane & 15)) * SH + (lane >> 4) * 8;
    const int bRowOff = (wx * 32 + (lane >> 4) * 8 + (lane & 7)) * SH +
                        ((lane >> 3) & 1) * 8;

    for (int unit_i = 0; unit_i < 2; unit_i++) {
        const int unit = blockIdx.x * 2 + unit_i;
        // triangle mapping: unit -> (I, J) with I <= J
        int u = unit;
        int I = 0;
        while (u >= NTILE - I) { u -= NTILE - I; I++; }
        const int J = I + u;
        const int rowBase = I * BM;
        const int colBase = J * BN;
        const bool diag = (I == J);

        __syncthreads();  // previous unit done with smem (labels + buffers)
        if (tid < 128) s_lr[tid] = (int)labels[rowBase + tid];
        else s_lc[tid - 128] = (int)labels[colBase + tid - 128];

        float acc[4][4][4];
#pragma unroll
        for (int mt = 0; mt < 4; mt++)
#pragma unroll
            for (int nt = 0; nt < 4; nt++)
#pragma unroll
                for (int q = 0; q < 4; q++) acc[mt][nt][q] = 0.0f;

        // ---- prefetch stage 0 ----
        {
            const __half* srcA = g_e + (size_t)rowBase * D;
            const __half* srcB = g_e + (size_t)colBase * D;
#pragma unroll
            for (int i = 0; i < 4; i++) {
                int idx = tid + i * 256;
                int row = idx >> 3, q = idx & 7;
                CP_ASYNC16(sb + row * 144 + q * 16,
                           srcA + (size_t)row * D + q * 8);
                if (!diag)
                    CP_ASYNC16(sb + 2 * BUF_HALFS * 2 + row * 144 + q * 16,
                               srcB + (size_t)row * D + q * 8);
            }
            CP_COMMIT();
        }

        for (int st = 0; st < NSTG; st++) {
            const int cur = st & 1;
            if (st + 1 < NSTG) {
                const int nxt = (st + 1) & 1;
                const int k0 = (st + 1) * BKH;
                const __half* srcA = g_e + (size_t)rowBase * D + k0;
                const __half* srcB = g_e + (size_t)colBase * D + k0;
#pragma unroll
                for (int i = 0; i < 4; i++) {
                    int idx = tid + i * 256;
                    int row = idx >> 3, q = idx & 7;
                    CP_ASYNC16(sb + nxt * BUF_HALFS * 2 + row * 144 + q * 16,
                               srcA + (size_t)row * D + q * 8);
                    if (!diag)
                        CP_ASYNC16(
                            sb + (2 + nxt) * BUF_HALFS * 2 + row * 144 + q * 16,
                            srcB + (size_t)row * D + q * 8);
                }
                CP_COMMIT();
                CP_WAIT(1);
            } else {
                CP_WAIT(0);
            }
            __syncthreads();

            const uint32_t baseA = sb + cur * BUF_HALFS * 2;
            const uint32_t baseB =
                diag ? baseA : (sb + (2 + cur) * BUF_HALFS * 2);
#pragma unroll
            for (int ks = 0; ks < 4; ks++) {
                uint32_t a[4][4], b[4][2];
#pragma unroll
                for (int mt = 0; mt < 4; mt++)
                    LDSM_X4(a[mt][0], a[mt][1], a[mt][2], a[mt][3],
                            baseA + (aRowOff + mt * 16 * SH + ks * 16) * 2);
#pragma unroll
                for (int p = 0; p < 2; p++)
                    LDSM_X4(b[2 * p][0], b[2 * p][1], b[2 * p + 1][0],
                            b[2 * p + 1][1],
                            baseB + (bRowOff + p * 16 * SH + ks * 16) * 2);
#pragma unroll
                for (int mt = 0; mt < 4; mt++)
#pragma unroll
                    for (int nt = 0; nt < 4; nt++)
                        mma_f16(acc[mt][nt], a[mt], b[nt]);
            }
            __syncthreads();
        }

        // ---- mining: rows and cols are both anchors ----------------------
        const float INF = __int_as_float(0x7f800000);
        float rp[4][2], rn[4][2];
        float cpm[4][2], cnm[4][2];
#pragma unroll
        for (int i = 0; i < 4; i++)
#pragma unroll
            for (int h = 0; h < 2; h++) {
                rp[i][h] = INF; rn[i][h] = -INF;
                cpm[i][h] = INF; cnm[i][h] = -INF;
            }

#pragma unroll
        for (int nt = 0; nt < 4; nt++) {
            const int c0 = colBase + wx * 32 + nt * 8 + 2 * t;
            const int lc0 = s_lc[wx * 32 + nt * 8 + 2 * t];
            const int lc1 = s_lc[wx * 32 + nt * 8 + 2 * t + 1];
#pragma unroll
            for (int mt = 0; mt < 4; mt++) {
                const int r0 = rowBase + wy * 64 + mt * 16 + g;
                const int r1 = r0 + 8;
                const int lr0 = s_lr[wy * 64 + mt * 16 + g];
                const int lr1 = s_lr[wy * 64 + mt * 16 + g + 8];
                const float d0 = acc[mt][nt][0], d1 = acc[mt][nt][1];
                const float d2 = acc[mt][nt][2], d3 = acc[mt][nt][3];
                if (lr0 == lc0) {
                    if (r0 != c0) { rp[mt][0] = fminf(rp[mt][0], d0);
                                    cpm[nt][0] = fminf(cpm[nt][0], d0); }
                } else { rn[mt][0] = fmaxf(rn[mt][0], d0);
                         cnm[nt][0] = fmaxf(cnm[nt][0], d0); }
                if (lr0 == lc1) {
                    if (r0 != c0 + 1) { rp[mt][0] = fminf(rp[mt][0], d1);
                                        cpm[nt][1] = fminf(cpm[nt][1], d1); }
                } else { rn[mt][0] = fmaxf(rn[mt][0], d1);
                         cnm[nt][1] = fmaxf(cnm[nt][1], d1); }
                if (lr1 == lc0) {
                    if (r1 != c0) { rp[mt][1] = fminf(rp[mt][1], d2);
                                    cpm[nt][0] = fminf(cpm[nt][0], d2); }
                } else { rn[mt][1] = fmaxf(rn[mt][1], d2);
                         cnm[nt][0] = fmaxf(cnm[nt][0], d2); }
                if (lr1 == lc1) {
                    if (r1 != c0 + 1) { rp[mt][1] = fminf(rp[mt][1], d3);
                                        cpm[nt][1] = fminf(cpm[nt][1], d3); }
                } else { rn[mt][1] = fmaxf(rn[mt][1], d3);
                         cnm[nt][1] = fmaxf(cnm[nt][1], d3); }
            }
        }

        // row-anchor reduce across t lanes
#pragma unroll
        for (int mt = 0; mt < 4; mt++)
#pragma unroll
            for (int h = 0; h < 2; h++) {
                float p = rp[mt][h], n = rn[mt][h];
                p = fminf(p, __shfl_xor_sync(0xffffffffu, p, 1));
                p = fminf(p, __shfl_xor_sync(0xffffffffu, p, 2));
                n = fmaxf(n, __shfl_xor_sync(0xffffffffu, n, 1));
                n = fmaxf(n, __shfl_xor_sync(0xffffffffu, n, 2));
                if (t == 0) {
                    int r = rowBase + wy * 64 + mt * 16 + g + h * 8;
                    if (p < 1e30f)
                        atomicMin(reinterpret_cast<int*>(&g_pkey[r]),
                                  __float_as_int(p + 4.0f));
                    if (n > -1e30f)
                        atomicMax(reinterpret_cast<int*>(&g_nkey[r]),
                                  __float_as_int(n + 4.0f));
                }
            }

        // col-anchor reduce across g lanes
#pragma unroll
        for (int nt = 0; nt < 4; nt++)
#pragma unroll
            for (int h = 0; h < 2; h++) {
                float p = cpm[nt][h], n = cnm[nt][h];
                p = fminf(p, __shfl_xor_sync(0xffffffffu, p, 4));
                p = fminf(p, __shfl_xor_sync(0xffffffffu, p, 8));
                p = fminf(p, __shfl_xor_sync(0xffffffffu, p, 16));
                n = fmaxf(n, __shfl_xor_sync(0xffffffffu, n, 4));
                n = fmaxf(n, __shfl_xor_sync(0xffffffffu, n, 8));
                n = fmaxf(n, __shfl_xor_sync(0xffffffffu, n, 16));
                if (g == 0) {
                    int c = colBase + wx * 32 + nt * 8 + 2 * t + h;
                    if (p < 1e30f)
                        atomicMin(reinterpret_cast<int*>(&g_pkey[c]),
                                  __float_as_int(p + 4.0f));
                    if (n > -1e30f)
                        atomicMax(reinterpret_cast<int*>(&g_nkey[c]),
                                  __float_as_int(n + 4.0f));
                }
            }
    }

    // ---- last CTA computes the final loss ---------------------------------
    __threadfence();
    __syncthreads();
    if (tid == 0) {
        unsigned int v = atomicAdd(&g_done, 1u);
        s_last = (v == NCTA - 1);
    }
    __syncthreads();
    if (!s_last) return;
    __threadfence();

    float sum = 0.0f, cnt = 0.0f;
    for (int i = tid; i < N; i += 256) {
        float pk = g_pkey[i];
        float nk = g_nkey[i];
        if (pk < 1e30f) {
            cnt += 1.0f;
            float dap = sqrtf(fmaxf(2.0f - 2.0f * (pk - 4.0f), 0.0f) + 1e-12f);
            float dan = (nk > 0.0f)
                ? sqrtf(fmaxf(2.0f - 2.0f * (nk - 4.0f), 0.0f) + 1e-12f)
                : 1e30f;
            sum += fmaxf(dap - dan + MARGIN, 0.0f);
        }
    }
#pragma unroll
    for (int o = 16; o > 0; o >>= 1) {
        sum += __shfl_xor_sync(0xffffffffu, sum, o);
        cnt += __shfl_xor_sync(0xffffffffu, cnt, o);
    }
    __shared__ float rs[8], rc[8];
    if ((tid & 31) == 0) { rs[tid >> 5] = sum; rc[tid >> 5] = cnt; }
    __syncthreads();
    if (tid == 0) {
        float S = 0.0f, C = 0.0f;
#pragma unroll
        for (int w = 0; w < 8; w++) { S += rs[w]; C += rc[w]; }
        out[0] = S / fmaxf(C, 1.0f);
        g_done = 0;  // reset for next graph replay
    }
}

// ---------------------------------------------------------------------------
extern "C" void kernel_launch(void* const* d_in, const int* in_sizes, int n_in,
                              void* d_out, int out_size) {
    const float* emb = (const float*)d_in[0];
    const long long* labels = (const long long*)d_in[1];
    float* out = (float*)d_out;

    static int configured = 0;
    if (!configured) {
        cudaFuncSetAttribute(mine_mma, cudaFuncAttributeMaxDynamicSharedMemorySize,
                             SMEM_BYTES);
        configured = 1;
    }

    normalize_kernel<<<N / 8, 256>>>(emb);
    mine_mma<<<NCTA, 256, SMEM_BYTES>>>(labels, out);
}

// round 15
// speedup vs baseline: 1.1210x; 1.0315x over previous
#include <cuda_runtime.h>
#include <cuda_fp16.h>
#include <stdint.h>

#define N 4096
#define D 768
#define BM 128
#define BN 128
#define BKH 64            // halfs per pipeline stage
#define NSTG (D / BKH)    // 12
#define MARGIN 1.0f
#define SH 72             // halfs per smem row (144 B) - conflict-free pad
#define BUF_HALFS (128 * SH)            // 9216 halfs = 18432 B
#define SMEM_BYTES (4 * BUF_HALFS * 2)  // 73728

#define NTILE 32          // 4096/128
#define NUNITS (NTILE * (NTILE + 1) / 2)  // 528 triangle units
#define NCTA (NUNITS / 2)                 // 264 CTAs, 2 units each (one wave)

__device__ __align__(128) __half g_e[N * D];  // normalized fp16 embeddings
__device__ float g_pkey[N];  // min positive dot + 4 (inf if none)
__device__ float g_nkey[N];  // max negative dot + 4 (0 if none)
__device__ unsigned int g_done = 0;

// ---------------- PTX helpers ---------------------------------------------
__device__ __forceinline__ uint32_t smem_u32(const void* p) {
    uint32_t a;
    asm("{ .reg .u64 t; cvta.to.shared.u64 t, %1; cvt.u32.u64 %0, t; }"
        : "=r"(a) : "l"(p));
    return a;
}
#define CP_ASYNC16(dst, src) \
    asm volatile("cp.async.cg.shared.global [%0], [%1], 16;" \
                 :: "r"(dst), "l"(src) : "memory")
#define CP_COMMIT() asm volatile("cp.async.commit_group;" ::: "memory")
#define CP_WAIT(n)  asm volatile("cp.async.wait_group %0;" :: "n"(n) : "memory")

#define LDSM_X4(r0, r1, r2, r3, addr) \
    asm volatile("ldmatrix.sync.aligned.m8n8.x4.shared.b16 {%0,%1,%2,%3}, [%4];" \
                 : "=r"(r0), "=r"(r1), "=r"(r2), "=r"(r3) : "r"(addr))

__device__ __forceinline__ void mma_f16(float* d, const uint32_t* a,
                                        const uint32_t* b) {
    asm volatile(
        "mma.sync.aligned.m16n8k16.row.col.f32.f16.f16.f32 "
        "{%0,%1,%2,%3}, {%4,%5,%6,%7}, {%8,%9}, {%0,%1,%2,%3};"
        : "+f"(d[0]), "+f"(d[1]), "+f"(d[2]), "+f"(d[3])
        : "r"(a[0]), "r"(a[1]), "r"(a[2]), "r"(a[3]), "r"(b[0]), "r"(b[1]));
}

// ---------------------------------------------------------------------------
// Warp-per-row normalize + fp16 convert; inits per-row mining keys.
__global__ void normalize_kernel(const float* __restrict__ emb) {
    const int warp = threadIdx.x >> 5;
    const int lane = threadIdx.x & 31;
    const int row = blockIdx.x * 8 + warp;
    if (lane == 0) {
        g_pkey[row] = __int_as_float(0x7f800000);  // +inf
        g_nkey[row] = 0.0f;                        // sentinel
    }
    const float4* src = (const float4*)(emb + (size_t)row * D);
    float4 v[6];
    float s = 0.0f;
#pragma unroll
    for (int i = 0; i < 6; i++) {
        v[i] = src[lane + i * 32];
        s += v[i].x * v[i].x + v[i].y * v[i].y + v[i].z * v[i].z +
             v[i].w * v[i].w;
    }
#pragma unroll
    for (int o = 16; o > 0; o >>= 1) s += __shfl_xor_sync(0xffffffffu, s, o);
    float inv = 1.0f / fmaxf(sqrtf(s), 1e-12f);
    uint2* dst = (uint2*)(g_e + (size_t)row * D);
#pragma unroll
    for (int i = 0; i < 6; i++) {
        __half2 h01 = __floats2half2_rn(v[i].x * inv, v[i].y * inv);
        __half2 h23 = __floats2half2_rn(v[i].z * inv, v[i].w * inv);
        uint2 u;
        u.x = *reinterpret_cast<uint32_t*>(&h01);
        u.y = *reinterpret_cast<uint32_t*>(&h23);
        dst[lane + i * 32] = u;
    }
}

// ---------------------------------------------------------------------------
// Two upper-triangle 128x128 Gram tiles per CTA (single wave: 264 CTAs at
// occupancy 2). fp16 m16n8k16 MMA via ldmatrix, double-buffered cp.async
// pipeline (R8 structure, byte-exact). Batch-hard mining in dot domain with
// rows AND cols as anchors; diagonal tiles skip the redundant col-anchor
// update. Last CTA computes the final scalar loss.
__global__ void __launch_bounds__(256, 2)
mine_mma(const long long* __restrict__ labels, float* __restrict__ out) {
    extern __shared__ __half smem[];
    const uint32_t sb = smem_u32(smem);
    __shared__ int s_lr[128], s_lc[128];
    __shared__ int s_last;

    const int tid = threadIdx.x;
    const int lane = tid & 31;
    const int warp = tid >> 5;
    const int wy = warp >> 2;   // 0..1
    const int wx = warp & 3;    // 0..3
    const int g = lane >> 2;    // 0..7
    const int t = lane & 3;     // 0..3

    // per-lane LDSM base offsets (half units within a buffer)
    const int aRowOff = (wy * 64 + (lane & 15)) * SH + (lane >> 4) * 8;
    const int bRowOff = (wx * 32 + (lane >> 4) * 8 + (lane & 7)) * SH +
                        ((lane >> 3) & 1) * 8;

    for (int unit_i = 0; unit_i < 2; unit_i++) {
        const int unit = blockIdx.x * 2 + unit_i;
        // triangle mapping: unit -> (I, J) with I <= J
        int u = unit;
        int I = 0;
        while (u >= NTILE - I) { u -= NTILE - I; I++; }
        const int J = I + u;
        const int rowBase = I * BM;
        const int colBase = J * BN;

        __syncthreads();  // previous unit done with smem (labels + buffers)
        if (tid < 128) s_lr[tid] = (int)labels[rowBase + tid];
        else s_lc[tid - 128] = (int)labels[colBase + tid - 128];

        float acc[4][4][4];
#pragma unroll
        for (int mt = 0; mt < 4; mt++)
#pragma unroll
            for (int nt = 0; nt < 4; nt++)
#pragma unroll
                for (int q = 0; q < 4; q++) acc[mt][nt][q] = 0.0f;

        // ---- prefetch stage 0 ----
        {
            const __half* srcA = g_e + (size_t)rowBase * D;
            const __half* srcB = g_e + (size_t)colBase * D;
#pragma unroll
            for (int i = 0; i < 4; i++) {
                int idx = tid + i * 256;
                int row = idx >> 3, q = idx & 7;
                CP_ASYNC16(sb + row * 144 + q * 16,
                           srcA + (size_t)row * D + q * 8);
                CP_ASYNC16(sb + 2 * BUF_HALFS * 2 + row * 144 + q * 16,
                           srcB + (size_t)row * D + q * 8);
            }
            CP_COMMIT();
        }

        for (int st = 0; st < NSTG; st++) {
            const int cur = st & 1;
            if (st + 1 < NSTG) {
                const int nxt = (st + 1) & 1;
                const int k0 = (st + 1) * BKH;
                const __half* srcA = g_e + (size_t)rowBase * D + k0;
                const __half* srcB = g_e + (size_t)colBase * D + k0;
#pragma unroll
                for (int i = 0; i < 4; i++) {
                    int idx = tid + i * 256;
                    int row = idx >> 3, q = idx & 7;
                    CP_ASYNC16(sb + nxt * BUF_HALFS * 2 + row * 144 + q * 16,
                               srcA + (size_t)row * D + q * 8);
                    CP_ASYNC16(
                        sb + (2 + nxt) * BUF_HALFS * 2 + row * 144 + q * 16,
                        srcB + (size_t)row * D + q * 8);
                }
                CP_COMMIT();
                CP_WAIT(1);
            } else {
                CP_WAIT(0);
            }
            __syncthreads();

            const uint32_t baseA = sb + cur * BUF_HALFS * 2;
            const uint32_t baseB = sb + (2 + cur) * BUF_HALFS * 2;
#pragma unroll
            for (int ks = 0; ks < 4; ks++) {
                uint32_t a[4][4], b[4][2];
#pragma unroll
                for (int mt = 0; mt < 4; mt++)
                    LDSM_X4(a[mt][0], a[mt][1], a[mt][2], a[mt][3],
                            baseA + (aRowOff + mt * 16 * SH + ks * 16) * 2);
#pragma unroll
                for (int p = 0; p < 2; p++)
                    LDSM_X4(b[2 * p][0], b[2 * p][1], b[2 * p + 1][0],
                            b[2 * p + 1][1],
                            baseB + (bRowOff + p * 16 * SH + ks * 16) * 2);
#pragma unroll
                for (int mt = 0; mt < 4; mt++)
#pragma unroll
                    for (int nt = 0; nt < 4; nt++)
                        mma_f16(acc[mt][nt], a[mt], b[nt]);
            }
            __syncthreads();
        }

        // ---- mining: rows and cols are both anchors ----------------------
        const float INF = __int_as_float(0x7f800000);
        float rp[4][2], rn[4][2];
        float cpm[4][2], cnm[4][2];
#pragma unroll
        for (int i = 0; i < 4; i++)
#pragma unroll
            for (int h = 0; h < 2; h++) {
                rp[i][h] = INF; rn[i][h] = -INF;
                cpm[i][h] = INF; cnm[i][h] = -INF;
            }

#pragma unroll
        for (int nt = 0; nt < 4; nt++) {
            const int c0 = colBase + wx * 32 + nt * 8 + 2 * t;
            const int lc0 = s_lc[wx * 32 + nt * 8 + 2 * t];
            const int lc1 = s_lc[wx * 32 + nt * 8 + 2 * t + 1];
#pragma unroll
            for (int mt = 0; mt < 4; mt++) {
                const int r0 = rowBase + wy * 64 + mt * 16 + g;
                const int r1 = r0 + 8;
                const int lr0 = s_lr[wy * 64 + mt * 16 + g];
                const int lr1 = s_lr[wy * 64 + mt * 16 + g + 8];
                const float d0 = acc[mt][nt][0], d1 = acc[mt][nt][1];
                const float d2 = acc[mt][nt][2], d3 = acc[mt][nt][3];
                if (lr0 == lc0) {
                    if (r0 != c0) { rp[mt][0] = fminf(rp[mt][0], d0);
                                    cpm[nt][0] = fminf(cpm[nt][0], d0); }
                } else { rn[mt][0] = fmaxf(rn[mt][0], d0);
                         cnm[nt][0] = fmaxf(cnm[nt][0], d0); }
                if (lr0 == lc1) {
                    if (r0 != c0 + 1) { rp[mt][0] = fminf(rp[mt][0], d1);
                                        cpm[nt][1] = fminf(cpm[nt][1], d1); }
                } else { rn[mt][0] = fmaxf(rn[mt][0], d1);
                         cnm[nt][1] = fmaxf(cnm[nt][1], d1); }
                if (lr1 == lc0) {
                    if (r1 != c0) { rp[mt][1] = fminf(rp[mt][1], d2);
                                    cpm[nt][0] = fminf(cpm[nt][0], d2); }
                } else { rn[mt][1] = fmaxf(rn[mt][1], d2);
                         cnm[nt][0] = fmaxf(cnm[nt][0], d2); }
                if (lr1 == lc1) {
                    if (r1 != c0 + 1) { rp[mt][1] = fminf(rp[mt][1], d3);
                                        cpm[nt][1] = fminf(cpm[nt][1], d3); }
                } else { rn[mt][1] = fmaxf(rn[mt][1], d3);
                         cnm[nt][1] = fmaxf(cnm[nt][1], d3); }
            }
        }

        // row-anchor reduce across t lanes
#pragma unroll
        for (int mt = 0; mt < 4; mt++)
#pragma unroll
            for (int h = 0; h < 2; h++) {
                float p = rp[mt][h], n = rn[mt][h];
                p = fminf(p, __shfl_xor_sync(0xffffffffu, p, 1));
                p = fminf(p, __shfl_xor_sync(0xffffffffu, p, 2));
                n = fmaxf(n, __shfl_xor_sync(0xffffffffu, n, 1));
                n = fmaxf(n, __shfl_xor_sync(0xffffffffu, n, 2));
                if (t == 0) {
                    int r = rowBase + wy * 64 + mt * 16 + g + h * 8;
                    if (p < 1e30f)
                        atomicMin(reinterpret_cast<int*>(&g_pkey[r]),
                                  __float_as_int(p + 4.0f));
                    if (n > -1e30f)
                        atomicMax(reinterpret_cast<int*>(&g_nkey[r]),
                                  __float_as_int(n + 4.0f));
                }
            }

        // col-anchor reduce across g lanes (skip on diagonal tiles: they
        // duplicate the row-anchor updates exactly)
        if (rowBase != colBase) {
#pragma unroll
            for (int nt = 0; nt < 4; nt++)
#pragma unroll
                for (int h = 0; h < 2; h++) {
                    float p = cpm[nt][h], n = cnm[nt][h];
                    p = fminf(p, __shfl_xor_sync(0xffffffffu, p, 4));
                    p = fminf(p, __shfl_xor_sync(0xffffffffu, p, 8));
                    p = fminf(p, __shfl_xor_sync(0xffffffffu, p, 16));
                    n = fmaxf(n, __shfl_xor_sync(0xffffffffu, n, 4));
                    n = fmaxf(n, __shfl_xor_sync(0xffffffffu, n, 8));
                    n = fmaxf(n, __shfl_xor_sync(0xffffffffu, n, 16));
                    if (g == 0) {
                        int c = colBase + wx * 32 + nt * 8 + 2 * t + h;
                        if (p < 1e30f)
                            atomicMin(reinterpret_cast<int*>(&g_pkey[c]),
                                      __float_as_int(p + 4.0f));
                        if (n > -1e30f)
                            atomicMax(reinterpret_cast<int*>(&g_nkey[c]),
                                      __float_as_int(n + 4.0f));
                    }
                }
        }
    }

    // ---- last CTA computes the final loss ---------------------------------
    __threadfence();
    __syncthreads();
    if (tid == 0) {
        unsigned int v = atomicAdd(&g_done, 1u);
        s_last = (v == NCTA - 1);
    }
    __syncthreads();
    if (!s_last) return;
    __threadfence();

    float sum = 0.0f, cnt = 0.0f;
    for (int i = tid; i < N; i += 256) {
        float pk = g_pkey[i];
        float nk = g_nkey[i];
        if (pk < 1e30f) {
            cnt += 1.0f;
            float dap = sqrtf(fmaxf(2.0f - 2.0f * (pk - 4.0f), 0.0f) + 1e-12f);
            float dan = (nk > 0.0f)
                ? sqrtf(fmaxf(2.0f - 2.0f * (nk - 4.0f), 0.0f) + 1e-12f)
                : 1e30f;
            sum += fmaxf(dap - dan + MARGIN, 0.0f);
        }
    }
#pragma unroll
    for (int o = 16; o > 0; o >>= 1) {
        sum += __shfl_xor_sync(0xffffffffu, sum, o);
        cnt += __shfl_xor_sync(0xffffffffu, cnt, o);
    }
    __shared__ float rs[8], rc[8];
    if ((tid & 31) == 0) { rs[tid >> 5] = sum; rc[tid >> 5] = cnt; }
    __syncthreads();
    if (tid == 0) {
        float S = 0.0f, C = 0.0f;
#pragma unroll
        for (int w = 0; w < 8; w++) { S += rs[w]; C += rc[w]; }
        out[0] = S / fmaxf(C, 1.0f);
        g_done = 0;  // reset for next graph replay
    }
}

// ---------------------------------------------------------------------------
extern "C" void kernel_launch(void* const* d_in, const int* in_sizes, int n_in,
                              void* d_out, int out_size) {
    const float* emb = (const float*)d_in[0];
    const long long* labels = (const long long*)d_in[1];
    float* out = (float*)d_out;

    static int configured = 0;
    if (!configured) {
        cudaFuncSetAttribute(mine_mma, cudaFuncAttributeMaxDynamicSharedMemorySize,
                             SMEM_BYTES);
        configured = 1;
    }

    normalize_kernel<<<N / 8, 256>>>(emb);
    mine_mma<<<NCTA, 256, SMEM_BYTES>>>(labels, out);
}